// round 6
// baseline (speedup 1.0000x reference)
#include <cuda_runtime.h>

#define BATCH 2048
#define NE    2048
#define NDIMS 128
#define SPEC_C 6.5f

#define TILE   128
#define DCHUNK 64
#define SROW   132   // padded smem row stride (floats): aligned, conflict-free compute LDS.128

#define SMEM_BYTES (2 * DCHUNK * SROW * 4)

// Scratch (device globals: allocation-free rule)
__device__ float g_xs[BATCH * NDIMS];   // 2C * attn-scaled inputs
__device__ float g_es[NE * NDIMS];      // 2C * attn-scaled exemplars
__device__ float g_sumx[BATCH];         // -C * sum_d attn*X
__device__ float g_sume[NE];            // -C * sum_d attn*E

// ---------------------------------------------------------------------------
// Pre-scale: Xs = 2C*attn*X, Es = 2C*attn*E, plus row sums scaled by -C.
// ---------------------------------------------------------------------------
__global__ void prep_kernel(const float* __restrict__ X,
                            const float* __restrict__ E,
                            const float* __restrict__ attn) {
    const int warp = threadIdx.x >> 5;
    const int lane = threadIdx.x & 31;
    const int row  = blockIdx.x * 8 + warp;

    const float* src  = blockIdx.y ? E : X;
    float*       dst  = blockIdx.y ? g_es : g_xs;
    float*       dsum = blockIdx.y ? g_sume : g_sumx;

    const float k = 2.0f * SPEC_C;
    float4 x = reinterpret_cast<const float4*>(src + (size_t)row * NDIMS)[lane];
    float4 a = reinterpret_cast<const float4*>(attn)[lane];
    float4 s = make_float4(k * x.x * a.x, k * x.y * a.y, k * x.z * a.z, k * x.w * a.w);
    reinterpret_cast<float4*>(dst + (size_t)row * NDIMS)[lane] = s;

    float t = (s.x + s.y) + (s.z + s.w);
    #pragma unroll
    for (int off = 16; off > 0; off >>= 1)
        t += __shfl_xor_sync(0xffffffffu, t, off);
    if (lane == 0) dsum[row] = -0.5f * t;   // = -C * sum(attn*x)
}

// 64 FMNMX (alu) + 64 FADD (fma) on the given register buffers
#define COMPUTE_D(XA, XB, EA, EB)                                              \
    do {                                                                       \
        const float xv[8] = {(XA).x, (XA).y, (XA).z, (XA).w,                   \
                             (XB).x, (XB).y, (XB).z, (XB).w};                  \
        const float ev[8] = {(EA).x, (EA).y, (EA).z, (EA).w,                   \
                             (EB).x, (EB).y, (EB).z, (EB).w};                  \
        _Pragma("unroll")                                                      \
        for (int i_ = 0; i_ < 8; ++i_)                                         \
            _Pragma("unroll")                                                  \
            for (int j_ = 0; j_ < 8; ++j_)                                     \
                acc[i_][j_] += fminf(xv[i_], ev[j_]);                          \
    } while (0)

// ---------------------------------------------------------------------------
// Main: out[b,e] = exp( sumx'[b] + sume'[e] + sum_d min(Xs,Es) )
// 128x128 tile / block, 256 threads, 8x8 micro-tile, occ 2, DCHUNK 64.
// Inner loop software-pipelined: LDS.128 for d+1 issued ~128 slots before use.
// ---------------------------------------------------------------------------
__global__ __launch_bounds__(256, 2)
void alcove_kernel(float* __restrict__ out) {
    extern __shared__ float smem[];
    float* sx = smem;                  // [DCHUNK][SROW]
    float* se = smem + DCHUNK * SROW;  // [DCHUNK][SROW]

    const int tid = threadIdx.x;
    const int tx  = tid & 15;
    const int ty  = tid >> 4;
    const int b0  = blockIdx.y * TILE;
    const int e0  = blockIdx.x * TILE;

    float acc[8][8];
    #pragma unroll
    for (int i = 0; i < 8; ++i)
        #pragma unroll
        for (int j = 0; j < 8; ++j) acc[i][j] = 0.f;

    // staging decomposition: thread -> (q = d-quad 0..15, r = row-within-16)
    const int q  = tid & 15;
    const int r  = tid >> 4;
    const int qh = q >> 1;

    const float* sxp = sx + ty * 4;
    const float* sep = se + tx * 4;

    for (int dc = 0; dc < NDIMS; dc += DCHUNK) {
        __syncthreads();
        // Stage gmem [row][d] -> smem [d][row] (transpose): 8 passes of 16 rows
        #pragma unroll
        for (int p = 0; p < 8; ++p) {
            const int row = r + p * 16;
            const float4 vx = *reinterpret_cast<const float4*>(
                &g_xs[(size_t)(b0 + row) * NDIMS + dc + q * 4]);
            const float4 ve = *reinterpret_cast<const float4*>(
                &g_es[(size_t)(e0 + row) * NDIMS + dc + q * 4]);
            const float xa[4] = {vx.x, vx.y, vx.z, vx.w};
            const float ea[4] = {ve.x, ve.y, ve.z, ve.w};
            #pragma unroll
            for (int s = 0; s < 4; ++s) {
                const int k = (s + qh) & 3;           // rotation: spreads STS banks
                const int d = q * 4 + k;
                sx[d * SROW + row] = xa[k];
                se[d * SROW + row] = ea[k];
            }
        }
        __syncthreads();

        // preload d = 0
        float4 xa = *reinterpret_cast<const float4*>(sxp);
        float4 xb = *reinterpret_cast<const float4*>(sxp + 64);
        float4 ea = *reinterpret_cast<const float4*>(sep);
        float4 eb = *reinterpret_cast<const float4*>(sep + 64);

        #pragma unroll 7
        for (int d = 0; d < DCHUNK - 1; ++d) {
            // prefetch d+1 (independent of current compute; hides LDS latency)
            const float4 nxa = *reinterpret_cast<const float4*>(sxp + (d + 1) * SROW);
            const float4 nxb = *reinterpret_cast<const float4*>(sxp + (d + 1) * SROW + 64);
            const float4 nea = *reinterpret_cast<const float4*>(sep + (d + 1) * SROW);
            const float4 neb = *reinterpret_cast<const float4*>(sep + (d + 1) * SROW + 64);

            COMPUTE_D(xa, xb, ea, eb);

            xa = nxa; xb = nxb; ea = nea; eb = neb;
        }
        COMPUTE_D(xa, xb, ea, eb);   // last d of the chunk
    }

    // Epilogue: out = exp( sumx' + sume' + acc )
    float sxr[8], ser[8];
    #pragma unroll
    for (int i = 0; i < 8; ++i) {
        const int ri = (i < 4) ? (ty * 4 + i) : (64 + ty * 4 + (i - 4));
        sxr[i] = g_sumx[b0 + ri];
    }
    #pragma unroll
    for (int j = 0; j < 8; ++j) {
        const int cj = (j < 4) ? (tx * 4 + j) : (64 + tx * 4 + (j - 4));
        ser[j] = g_sume[e0 + cj];
    }

    #pragma unroll
    for (int i = 0; i < 8; ++i) {
        const int ri = (i < 4) ? (ty * 4 + i) : (64 + ty * 4 + (i - 4));
        float res[8];
        #pragma unroll
        for (int j = 0; j < 8; ++j)
            res[j] = __expf((sxr[i] + ser[j]) + acc[i][j]);
        float* orow = out + (size_t)(b0 + ri) * NE + e0;
        *reinterpret_cast<float4*>(&orow[tx * 4])      = make_float4(res[0], res[1], res[2], res[3]);
        *reinterpret_cast<float4*>(&orow[64 + tx * 4]) = make_float4(res[4], res[5], res[6], res[7]);
    }
}

// ---------------------------------------------------------------------------
extern "C" void kernel_launch(void* const* d_in, const int* in_sizes, int n_in,
                              void* d_out, int out_size) {
    const float* X    = (const float*)d_in[0];  // (2048,128)
    const float* E    = (const float*)d_in[1];  // (2048,128)
    const float* attn = (const float*)d_in[2];  // (128,)
    float* out = (float*)d_out;                 // (2048,2048)

    cudaFuncSetAttribute(alcove_kernel,
                         cudaFuncAttributeMaxDynamicSharedMemorySize, SMEM_BYTES);

    dim3 gprep(BATCH / 8, 2);
    prep_kernel<<<gprep, 256>>>(X, E, attn);

    dim3 gmain(NE / TILE, BATCH / TILE);   // (16, 16) = 256 blocks
    alcove_kernel<<<gmain, 256, SMEM_BYTES>>>(out);
}

// round 7
// speedup vs baseline: 1.0375x; 1.0375x over previous
#include <cuda_runtime.h>

#define BATCH 2048
#define NE    2048
#define NDIMS 128
#define SPEC_C 6.5f
#define LOG2E 1.4426950408889634f

#define TILE   128
#define DCHUNK 64
#define SROW   132   // padded smem row stride (floats): aligned, conflict-free compute LDS.128

#define SMEM_BYTES (2 * DCHUNK * SROW * 4)

// Scratch (device globals: allocation-free rule)
__device__ float g_xs[BATCH * NDIMS];   // 2C*log2e * attn-scaled inputs
__device__ float g_es[NE * NDIMS];      // 2C*log2e * attn-scaled exemplars
__device__ float g_sumx[BATCH];         // -C*log2e * sum_d attn*X
__device__ float g_sume[NE];            // -C*log2e * sum_d attn*E

// ---------------------------------------------------------------------------
// Pre-scale by 2C*log2e so the main kernel is pure min/add and the epilogue
// is a bare ex2.approx.
// ---------------------------------------------------------------------------
__global__ void prep_kernel(const float* __restrict__ X,
                            const float* __restrict__ E,
                            const float* __restrict__ attn) {
    const int warp = threadIdx.x >> 5;
    const int lane = threadIdx.x & 31;
    const int row  = blockIdx.x * 8 + warp;

    const float* src  = blockIdx.y ? E : X;
    float*       dst  = blockIdx.y ? g_es : g_xs;
    float*       dsum = blockIdx.y ? g_sume : g_sumx;

    const float k = 2.0f * SPEC_C * LOG2E;
    float4 x = reinterpret_cast<const float4*>(src + (size_t)row * NDIMS)[lane];
    float4 a = reinterpret_cast<const float4*>(attn)[lane];
    float4 s = make_float4(k * x.x * a.x, k * x.y * a.y, k * x.z * a.z, k * x.w * a.w);
    reinterpret_cast<float4*>(dst + (size_t)row * NDIMS)[lane] = s;

    float t = (s.x + s.y) + (s.z + s.w);
    #pragma unroll
    for (int off = 16; off > 0; off >>= 1)
        t += __shfl_xor_sync(0xffffffffu, t, off);
    if (lane == 0) dsum[row] = -0.5f * t;   // = -C*log2e * sum(attn*x)
}

__device__ __forceinline__ float ex2f(float x) {
    float r;
    asm("ex2.approx.ftz.f32 %0, %1;" : "=f"(r) : "f"(x));
    return r;
}

// ---------------------------------------------------------------------------
// Main: out[b,e] = exp2( sumx'[b] + sume'[e] + sum_d min(Xs,Es) )
// 128x128 tile / block, 256 threads, 8x8 micro-tile, occ 2, DCHUNK 64.
// Inner loop: exactly 4 LDS.128 + 64 FMNMX (alu) + 64 FADD (fma) per warp-d;
// float4 components referenced directly (no array copies -> no MOVs).
// ---------------------------------------------------------------------------
__global__ __launch_bounds__(256, 2)
void alcove_kernel(float* __restrict__ out) {
    extern __shared__ float smem[];
    float* sx = smem;                  // [DCHUNK][SROW]
    float* se = smem + DCHUNK * SROW;  // [DCHUNK][SROW]

    const int tid = threadIdx.x;
    const int tx  = tid & 15;
    const int ty  = tid >> 4;
    const int b0  = blockIdx.y * TILE;
    const int e0  = blockIdx.x * TILE;

    float acc[8][8];
    #pragma unroll
    for (int i = 0; i < 8; ++i)
        #pragma unroll
        for (int j = 0; j < 8; ++j) acc[i][j] = 0.f;

    // staging decomposition: thread -> (q = d-quad 0..15, r = row-within-16)
    const int q  = tid & 15;
    const int r  = tid >> 4;
    const int qh = q >> 1;

    const float* sxp = sx + ty * 4;
    const float* sep = se + tx * 4;

    for (int dc = 0; dc < NDIMS; dc += DCHUNK) {
        __syncthreads();
        // Stage gmem [row][d] -> smem [d][row] (transpose): 8 passes of 16 rows
        #pragma unroll
        for (int p = 0; p < 8; ++p) {
            const int row = r + p * 16;
            const float4 vx = *reinterpret_cast<const float4*>(
                &g_xs[(size_t)(b0 + row) * NDIMS + dc + q * 4]);
            const float4 ve = *reinterpret_cast<const float4*>(
                &g_es[(size_t)(e0 + row) * NDIMS + dc + q * 4]);
            const float xa[4] = {vx.x, vx.y, vx.z, vx.w};
            const float ea[4] = {ve.x, ve.y, ve.z, ve.w};
            #pragma unroll
            for (int s = 0; s < 4; ++s) {
                const int k = (s + qh) & 3;           // rotation: spreads STS banks
                const int d = q * 4 + k;
                sx[d * SROW + row] = xa[k];
                se[d * SROW + row] = ea[k];
            }
        }
        __syncthreads();

        #pragma unroll 8
        for (int d = 0; d < DCHUNK; ++d) {
            const float4 xa = *reinterpret_cast<const float4*>(sxp + d * SROW);
            const float4 xb = *reinterpret_cast<const float4*>(sxp + d * SROW + 64);
            const float4 ea = *reinterpret_cast<const float4*>(sep + d * SROW);
            const float4 eb = *reinterpret_cast<const float4*>(sep + d * SROW + 64);

            // 64 fminf on direct components: FMNMX (alu) + FADD (fma), no MOVs
            #define ROWMIN(I, XC)                                   \
                acc[I][0] += fminf(XC, ea.x);                       \
                acc[I][1] += fminf(XC, ea.y);                       \
                acc[I][2] += fminf(XC, ea.z);                       \
                acc[I][3] += fminf(XC, ea.w);                       \
                acc[I][4] += fminf(XC, eb.x);                       \
                acc[I][5] += fminf(XC, eb.y);                       \
                acc[I][6] += fminf(XC, eb.z);                       \
                acc[I][7] += fminf(XC, eb.w);
            ROWMIN(0, xa.x) ROWMIN(1, xa.y) ROWMIN(2, xa.z) ROWMIN(3, xa.w)
            ROWMIN(4, xb.x) ROWMIN(5, xb.y) ROWMIN(6, xb.z) ROWMIN(7, xb.w)
            #undef ROWMIN
        }
    }

    // Epilogue: out = exp2( sumx' + sume' + acc )
    float sxr[8], ser[8];
    #pragma unroll
    for (int i = 0; i < 8; ++i) {
        const int ri = (i < 4) ? (ty * 4 + i) : (64 + ty * 4 + (i - 4));
        sxr[i] = g_sumx[b0 + ri];
    }
    #pragma unroll
    for (int j = 0; j < 8; ++j) {
        const int cj = (j < 4) ? (tx * 4 + j) : (64 + tx * 4 + (j - 4));
        ser[j] = g_sume[e0 + cj];
    }

    #pragma unroll
    for (int i = 0; i < 8; ++i) {
        const int ri = (i < 4) ? (ty * 4 + i) : (64 + ty * 4 + (i - 4));
        float res[8];
        #pragma unroll
        for (int j = 0; j < 8; ++j)
            res[j] = ex2f((sxr[i] + ser[j]) + acc[i][j]);
        float* orow = out + (size_t)(b0 + ri) * NE + e0;
        *reinterpret_cast<float4*>(&orow[tx * 4])      = make_float4(res[0], res[1], res[2], res[3]);
        *reinterpret_cast<float4*>(&orow[64 + tx * 4]) = make_float4(res[4], res[5], res[6], res[7]);
    }
}

// ---------------------------------------------------------------------------
extern "C" void kernel_launch(void* const* d_in, const int* in_sizes, int n_in,
                              void* d_out, int out_size) {
    const float* X    = (const float*)d_in[0];  // (2048,128)
    const float* E    = (const float*)d_in[1];  // (2048,128)
    const float* attn = (const float*)d_in[2];  // (128,)
    float* out = (float*)d_out;                 // (2048,2048)

    cudaFuncSetAttribute(alcove_kernel,
                         cudaFuncAttributeMaxDynamicSharedMemorySize, SMEM_BYTES);

    dim3 gprep(BATCH / 8, 2);
    prep_kernel<<<gprep, 256>>>(X, E, attn);

    dim3 gmain(NE / TILE, BATCH / TILE);   // (16, 16) = 256 blocks
    alcove_kernel<<<gmain, 256, SMEM_BYTES>>>(out);
}

// round 9
// speedup vs baseline: 1.1167x; 1.0763x over previous
#include <cuda_runtime.h>

#define BATCH 2048
#define NE    2048
#define NDIMS 128
#define SPEC_C 6.5f
#define LOG2E 1.4426950408889634f

#define TILE   128
#define DCHUNK 32
#define SROW   132   // padded smem row stride (floats)

// Scratch (device globals: allocation-free rule)
__device__ float g_xs[BATCH * NDIMS];   // u = C*log2e * attn * X
__device__ float g_es[NE * NDIMS];      // v = C*log2e * attn * E
__device__ float g_sumx[BATCH];         // -sum_d u
__device__ float g_sume[NE];            // -sum_d v

// ---------------------------------------------------------------------------
// Pre-scale by C*log2e; row sums negated.
//   |x-e|-term in exp2 domain: -|u-v|  =  2*min(u,v) - u - v
// ---------------------------------------------------------------------------
__global__ void prep_kernel(const float* __restrict__ X,
                            const float* __restrict__ E,
                            const float* __restrict__ attn) {
    const int warp = threadIdx.x >> 5;
    const int lane = threadIdx.x & 31;
    const int row  = blockIdx.x * 8 + warp;

    const float* src  = blockIdx.y ? E : X;
    float*       dst  = blockIdx.y ? g_es : g_xs;
    float*       dsum = blockIdx.y ? g_sume : g_sumx;

    const float k = SPEC_C * LOG2E;
    float4 x = reinterpret_cast<const float4*>(src + (size_t)row * NDIMS)[lane];
    float4 a = reinterpret_cast<const float4*>(attn)[lane];
    float4 s = make_float4(k * x.x * a.x, k * x.y * a.y, k * x.z * a.z, k * x.w * a.w);
    reinterpret_cast<float4*>(dst + (size_t)row * NDIMS)[lane] = s;

    float t = (s.x + s.y) + (s.z + s.w);
    #pragma unroll
    for (int off = 16; off > 0; off >>= 1)
        t += __shfl_xor_sync(0xffffffffu, t, off);
    if (lane == 0) dsum[row] = -t;
}

__device__ __forceinline__ float ex2f(float x) {
    float r;
    asm("ex2.approx.ftz.f32 %0, %1;" : "=f"(r) : "f"(x));
    return r;
}

// ---------------------------------------------------------------------------
// Main. 128x128 tile / block, 256 threads, 8x8 micro-tile, occ 2 (R1 chassis).
// Per-element pipe-balanced dual form:
//   j<5 (min-form):  acc += 2*min(u,v)        -> FMNMX(alu) + FFMA-imm(fma)
//   j>=5 (abs-form): acc -= |u-v|             -> 2x FADD (fma pipe only)
// Per warp-d: alu 80 cyc vs 128 before; fma 88 cyc. alu unclogged.
// ---------------------------------------------------------------------------
__global__ __launch_bounds__(256, 2)
void alcove_kernel(float* __restrict__ out) {
    __shared__ float sx[DCHUNK * SROW];
    __shared__ float se[DCHUNK * SROW];

    const int tid = threadIdx.x;
    const int tx  = tid & 15;
    const int ty  = tid >> 4;
    const int b0  = blockIdx.y * TILE;
    const int e0  = blockIdx.x * TILE;

    float acc[8][8];
    #pragma unroll
    for (int i = 0; i < 8; ++i)
        #pragma unroll
        for (int j = 0; j < 8; ++j) acc[i][j] = 0.f;

    // staging decomposition: thread -> (q = d-quad 0..7, r = row-within-32)
    const int q = tid & 7;
    const int r = tid >> 3;

    for (int dc = 0; dc < NDIMS; dc += DCHUNK) {
        __syncthreads();
        // Stage gmem [row][d] -> smem [d][row] (transpose)
        #pragma unroll
        for (int p = 0; p < 4; ++p) {
            const int row = r + p * 32;
            const float4 vx = *reinterpret_cast<const float4*>(
                &g_xs[(size_t)(b0 + row) * NDIMS + dc + q * 4]);
            const float4 ve = *reinterpret_cast<const float4*>(
                &g_es[(size_t)(e0 + row) * NDIMS + dc + q * 4]);
            sx[(q * 4 + 0) * SROW + row] = vx.x;
            sx[(q * 4 + 1) * SROW + row] = vx.y;
            sx[(q * 4 + 2) * SROW + row] = vx.z;
            sx[(q * 4 + 3) * SROW + row] = vx.w;
            se[(q * 4 + 0) * SROW + row] = ve.x;
            se[(q * 4 + 1) * SROW + row] = ve.y;
            se[(q * 4 + 2) * SROW + row] = ve.z;
            se[(q * 4 + 3) * SROW + row] = ve.w;
        }
        __syncthreads();

        #pragma unroll 4
        for (int d = 0; d < DCHUNK; ++d) {
            const float4 xa = *reinterpret_cast<const float4*>(&sx[d * SROW + ty * 4]);
            const float4 xb = *reinterpret_cast<const float4*>(&sx[d * SROW + 64 + ty * 4]);
            const float4 ea = *reinterpret_cast<const float4*>(&se[d * SROW + tx * 4]);
            const float4 eb = *reinterpret_cast<const float4*>(&se[d * SROW + 64 + tx * 4]);
            const float xv[8] = {xa.x, xa.y, xa.z, xa.w, xb.x, xb.y, xb.z, xb.w};
            const float ev[8] = {ea.x, ea.y, ea.z, ea.w, eb.x, eb.y, eb.z, eb.w};
            #pragma unroll
            for (int i = 0; i < 8; ++i) {
                // min-form columns (alu + fma)
                #pragma unroll
                for (int j = 0; j < 5; ++j)
                    acc[i][j] = fmaf(fminf(xv[i], ev[j]), 2.0f, acc[i][j]);
                // abs-form columns (fma pipe only)
                #pragma unroll
                for (int j = 5; j < 8; ++j)
                    acc[i][j] -= fabsf(xv[i] - ev[j]);
            }
        }
    }

    // Epilogue.
    float nsu[8], nsv[8];
    #pragma unroll
    for (int i = 0; i < 8; ++i) {
        const int ri = (i < 4) ? (ty * 4 + i) : (64 + ty * 4 + (i - 4));
        nsu[i] = g_sumx[b0 + ri];   // = -Su
    }
    #pragma unroll
    for (int j = 0; j < 8; ++j) {
        const int cj = (j < 4) ? (tx * 4 + j) : (64 + tx * 4 + (j - 4));
        nsv[j] = g_sume[e0 + cj];   // = -Sv
    }

    #pragma unroll
    for (int i = 0; i < 8; ++i) {
        const int ri = (i < 4) ? (ty * 4 + i) : (64 + ty * 4 + (i - 4));
        float res[8];
        #pragma unroll
        for (int j = 0; j < 5; ++j)   // min-form: arg = acc - Su - Sv
            res[j] = ex2f(acc[i][j] + (nsu[i] + nsv[j]));
        #pragma unroll
        for (int j = 5; j < 8; ++j)   // abs-form: arg = acc (already -sum|u-v|)
            res[j] = ex2f(acc[i][j]);
        float* orow = out + (size_t)(b0 + ri) * NE + e0;
        *reinterpret_cast<float4*>(&orow[tx * 4])      = make_float4(res[0], res[1], res[2], res[3]);
        *reinterpret_cast<float4*>(&orow[64 + tx * 4]) = make_float4(res[4], res[5], res[6], res[7]);
    }
}

// ---------------------------------------------------------------------------
extern "C" void kernel_launch(void* const* d_in, const int* in_sizes, int n_in,
                              void* d_out, int out_size) {
    const float* X    = (const float*)d_in[0];  // (2048,128)
    const float* E    = (const float*)d_in[1];  // (2048,128)
    const float* attn = (const float*)d_in[2];  // (128,)
    float* out = (float*)d_out;                 // (2048,2048)

    dim3 gprep(BATCH / 8, 2);
    prep_kernel<<<gprep, 256>>>(X, E, attn);

    dim3 gmain(NE / TILE, BATCH / TILE);   // (16, 16) = 256 blocks
    alcove_kernel<<<gmain, 256>>>(out);
}